// round 12
// baseline (speedup 1.0000x reference)
#include <cuda_runtime.h>
#include <cuda_fp16.h>
#include <math.h>
#include <stdint.h>

#define N_NODES 4096
#define N_EDGES 16384
#define D       64
#define BG      16
#define SLOPE   0.01f

#define TW      4160            // T row width: 4096 (k*64+f) + 64 bias cols
#define TWPAD   4352            // padded to 17*256 for GEMM tiling

// ---------------- device scratch ----------------
__device__ __half g_T[(size_t)N_NODES * TW];     // 34 MB per-node transformed table
__device__ __half g_We2RT[TWPAD * D];            // [c][d] reshaped We2 (+bias cols)
__device__ __half g_he_h[N_EDGES * D];
__device__ __half g_h_h[N_NODES * D];            // fp16 mirror of h
__device__ float g_h[N_NODES * D];
__device__ float g_agg[N_NODES * D];
__device__ float g_deg[N_NODES];
__device__ float g_Wi4[D * D * 4];
__device__ float g_Wh4[D * D * 4];
__device__ float g_q[D];
__device__ float g_e[N_NODES];
__device__ float g_a[N_NODES];
__device__ float g_emax[BG];
__device__ float g_asum[BG];
__device__ float g_rpool[BG * D];

__device__ __forceinline__ float lrelu(float x) { return x >= 0.f ? x : SLOPE * x; }
__device__ __forceinline__ float sigm(float x)  { return 1.f / (1.f + expf(-x)); }

__device__ __forceinline__ void atomicMaxF(float* addr, float v) {
    int* ai = (int*)addr;
    int old = *ai;
    while (__int_as_float(old) < v) {
        int assumed = old;
        old = atomicCAS(ai, assumed, __float_as_int(v));
        if (old == assumed) break;
    }
}

__device__ __forceinline__ void mma16816(float c[4],
                                         uint32_t a0, uint32_t a1, uint32_t a2, uint32_t a3,
                                         uint32_t b0, uint32_t b1) {
    asm volatile(
        "mma.sync.aligned.m16n8k16.row.col.f32.f16.f16.f32 "
        "{%0,%1,%2,%3}, {%4,%5,%6,%7}, {%8,%9}, {%0,%1,%2,%3};"
        : "+f"(c[0]), "+f"(c[1]), "+f"(c[2]), "+f"(c[3])
        : "r"(a0), "r"(a1), "r"(a2), "r"(a3), "r"(b0), "r"(b1));
}

__device__ __forceinline__ void ldsm_x4(uint32_t& r0, uint32_t& r1,
                                        uint32_t& r2, uint32_t& r3,
                                        const void* smem_ptr) {
    uint32_t addr;
    asm("{ .reg .u64 t; cvta.to.shared.u64 t, %1; cvt.u32.u64 %0, t; }"
        : "=r"(addr) : "l"(smem_ptr));
    asm volatile("ldmatrix.sync.aligned.m8n8.x4.shared.b16 {%0,%1,%2,%3}, [%4];"
                 : "=r"(r0), "=r"(r1), "=r"(r2), "=r"(r3) : "r"(addr));
}

__device__ __forceinline__ uint32_t smem_u32(const void* p) {
    uint32_t a;
    asm("{ .reg .u64 t; cvta.to.shared.u64 t, %1; cvt.u32.u64 %0, t; }"
        : "=r"(a) : "l"(p));
    return a;
}

#define CPA16(dst_u32, src_ptr) \
    asm volatile("cp.async.cg.shared.global [%0], [%1], 16;" :: "r"(dst_u32), "l"(src_ptr))
#define CPA_COMMIT() asm volatile("cp.async.commit_group;" ::: "memory")
#define CPA_WAIT1()  asm volatile("cp.async.wait_group 1;" ::: "memory")

// ---------------- prep kernels (fused) ----------------

// sections: [0,1088) we2rt | [1088,1152) gru | [1152,2176) zero agg/deg
__global__ void k_prep(const float* __restrict__ We2, const float* __restrict__ be2,
                       const float* __restrict__ Wih, const float* __restrict__ Whh) {
    int b = blockIdx.x;
    int t = threadIdx.x;
    if (b < 1088) {
        int idx = b * 256 + t;                 // < TWPAD*D
        int d = idx & 63, c = idx >> 6;
        float v = 0.f;
        if (c < 4096) {
            int k = c >> 6, f = c & 63;
            v = We2[k * 4096 + d * 64 + f];
        } else if (c < TW) {
            int f = c - 4096;
            v = be2[d * 64 + f];
        }
        g_We2RT[c * D + d] = __float2half(v);
    } else if (b < 1152) {
        int idx = (b - 1088) * 256 + t;        // < D*D*4
        int gg = idx & 3, f = (idx >> 2) & 63, k = idx >> 8;
        float vi = 0.f, vh = 0.f;
        if (gg < 3) {
            vi = Wih[(gg * 64 + f) * 64 + k];
            vh = Whh[(gg * 64 + f) * 64 + k];
        }
        g_Wi4[idx] = vi;
        g_Wh4[idx] = vh;
    } else {
        int idx = (b - 1152) * 256 + t;        // < N_NODES*D
        g_agg[idx] = 0.f;
        if (idx < N_NODES) g_deg[idx] = 0.f;
    }
}

// sections: [0, 262144) node init | [262144, 262144+1048576) edge init
__global__ void k_init(const float* __restrict__ x,
                       const float* __restrict__ W0,
                       const float* __restrict__ b0,
                       const float* __restrict__ ea,
                       const float* __restrict__ We1,
                       const float* __restrict__ be1,
                       const int* __restrict__ ei) {
    int gidx = blockIdx.x * blockDim.x + threadIdx.x;
    if (gidx < N_NODES * D) {
        int n = gidx >> 6, f = gidx & 63;
        float acc = b0[f];
        acc += x[n * 3 + 0] * W0[0 * D + f];
        acc += x[n * 3 + 1] * W0[1 * D + f];
        acc += x[n * 3 + 2] * W0[2 * D + f];
        float v = lrelu(acc);
        g_h[gidx] = v;
        g_h_h[gidx] = __float2half(v);
    } else {
        int idx = gidx - N_NODES * D;
        int e = idx >> 6, f = idx & 63;
        float acc = be1[f];
        acc += ea[e * 4 + 0] * We1[0 * D + f];
        acc += ea[e * 4 + 1] * We1[1 * D + f];
        acc += ea[e * 4 + 2] * We1[2 * D + f];
        acc += ea[e * 4 + 3] * We1[3 * D + f];
        g_he_h[idx] = __float2half(lrelu(acc));
        if (f == 0) {
            int dst = ei[N_EDGES + e];
            atomicAdd(&g_deg[dst], 1.f);   // deg zeroed by k_prep (prior launch)
        }
    }
}

// ---------------- per-iteration T GEMM ----------------
// T[n][c] = sum_d h[n,d] * We2RT[c][d], fp16 out.
// Block: 256 nodes x 256 cols (4 x 64-row phases); 512 thr; warps 2wm x 8wn, m32 x n32.
// sA double-buffered via cp.async (one phase lookahead); 2 barriers/phase.
__global__ void __launch_bounds__(512, 2) k_t_gemm() {
    extern __shared__ __half smem[];
    __half* sBT = smem;                       // [256][72]
    __half* sA0 = smem + 256 * 72;            // [2][64][72]
    __half* sSt = smem + (256 + 128) * 72;    // [64][264]
    int nbase = blockIdx.x * 256;
    int mbase0 = blockIdx.y * 256;
    int tid = threadIdx.x;

#pragma unroll
    for (int i = 0; i < 4; i++) {
        int u = tid + i * 512;
        int row = u >> 3, ch = u & 7;
        *(uint4*)&sBT[row * 72 + ch * 8] = *(const uint4*)&g_We2RT[(nbase + row) * D + ch * 8];
    }

    // preload phase-0 A (8 KB: 512 x 16B, one per thread)
    {
        int row = tid >> 3, ch = tid & 7;
        CPA16(smem_u32(&sA0[row * 72 + ch * 8]),
              (const char*)&g_h_h[(mbase0 + row) * D + ch * 8]);
    }
    CPA_COMMIT();

    int warp = tid >> 5, lane = tid & 31;
    int wm = warp & 1, wn = warp >> 1;        // 2 x 8 warp grid
    int g = lane >> 2, tig = lane & 3;
    int a_row = (lane & 7) + ((lane & 8) ? 8 : 0);
    int a_col8 = (lane & 16) ? 8 : 0;
    int b_row = (lane & 7) + ((lane & 16) ? 8 : 0);
    int b_col8 = (lane & 8) ? 8 : 0;

#pragma unroll
    for (int ms = 0; ms < 4; ms++) {
        __half* sA = sA0 + (ms & 1) * 64 * 72;
        // prefetch next phase's A into the other buffer (safe: previous phase's
        // compute on that buffer finished before its stage-barrier)
        if (ms + 1 < 4) {
            __half* sAn = sA0 + ((ms + 1) & 1) * 64 * 72;
            int row = tid >> 3, ch = tid & 7;
            CPA16(smem_u32(&sAn[row * 72 + ch * 8]),
                  (const char*)&g_h_h[(mbase0 + (ms + 1) * 64 + row) * D + ch * 8]);
        }
        CPA_COMMIT();      // uniform group count
        CPA_WAIT1();       // current phase's A resident
        __syncthreads();   // A visible to all; sSt reusable

        float c[2][4][4];
#pragma unroll
        for (int t = 0; t < 2; t++)
#pragma unroll
            for (int j = 0; j < 4; j++)
                c[t][j][0] = c[t][j][1] = c[t][j][2] = c[t][j][3] = 0.f;

#pragma unroll
        for (int s = 0; s < 4; s++) {
            int k0 = s * 16;
            uint32_t a[2][4], b[2][4];
#pragma unroll
            for (int t = 0; t < 2; t++)
                ldsm_x4(a[t][0], a[t][1], a[t][2], a[t][3],
                        &sA[(wm * 32 + t * 16 + a_row) * 72 + k0 + a_col8]);
#pragma unroll
            for (int jp = 0; jp < 2; jp++)
                ldsm_x4(b[jp][0], b[jp][1], b[jp][2], b[jp][3],
                        &sBT[(wn * 32 + jp * 16 + b_row) * 72 + k0 + b_col8]);
#pragma unroll
            for (int t = 0; t < 2; t++)
#pragma unroll
                for (int jp = 0; jp < 2; jp++) {
                    mma16816(c[t][2 * jp],     a[t][0], a[t][1], a[t][2], a[t][3],
                             b[jp][0], b[jp][1]);
                    mma16816(c[t][2 * jp + 1], a[t][0], a[t][1], a[t][2], a[t][3],
                             b[jp][2], b[jp][3]);
                }
        }

        // stage fragments (conflict-free)
#pragma unroll
        for (int t = 0; t < 2; t++)
#pragma unroll
            for (int j = 0; j < 4; j++) {
                int col = wn * 32 + j * 8 + 2 * tig;
                int r0 = wm * 32 + t * 16 + g;
                *(__half2*)&sSt[r0 * 264 + col] = __floats2half2_rn(c[t][j][0], c[t][j][1]);
                *(__half2*)&sSt[(r0 + 8) * 264 + col] = __floats2half2_rn(c[t][j][2], c[t][j][3]);
            }
        __syncthreads();

        // coalesced copy-out
        int mbase = mbase0 + ms * 64;
#pragma unroll
        for (int i = 0; i < 4; i++) {
            int u = tid + i * 512;
            int row = u >> 5, seg = u & 31;
            int col = nbase + seg * 8;
            if (col < TW)
                *(uint4*)&g_T[(size_t)(mbase + row) * TW + col] =
                    *(uint4*)&sSt[row * 264 + seg * 8];
        }
    }
}

// ---------------- loop kernels ----------------

// msg[e,f] = sum_k he[e,k] * T[src, k*64+f] + T[src, 4096+f]; scatter to agg.
// 32 edges/block (256 thr): 4 edges/warp, 8 lanes/edge, 8 cols/lane (LDG.128).
__global__ void k_msg(const int* __restrict__ ei) {
    int tid = threadIdx.x;
    int warp = tid >> 5, lane = tid & 31;
    int sub = lane >> 3, sl = lane & 7;
    int le = warp * 4 + sub;
    int e = blockIdx.x * 32 + le;
    __shared__ float sx[32][65];   // padded: kills 4-way bank conflict on broadcast
#pragma unroll
    for (int i = 0; i < 8; i++) {
        int idx = tid + i * 256;
        int l2 = idx >> 6, k = idx & 63;
        sx[l2][k] = __half2float(g_he_h[(blockIdx.x * 32 + l2) * D + k]);
    }
    __syncthreads();

    int src = ei[e];
    int dst = ei[N_EDGES + e];
    const __half* __restrict__ T = g_T + (size_t)src * TW;

    float acc[8];
    {
        uint4 b = *(const uint4*)&T[4096 + 8 * sl];
        const __half2* bh = (const __half2*)&b;
#pragma unroll
        for (int p = 0; p < 4; p++) {
            float2 v = __half22float2(bh[p]);
            acc[2 * p] = v.x;
            acc[2 * p + 1] = v.y;
        }
    }
#pragma unroll 4
    for (int k = 0; k < D; k++) {
        uint4 w = *(const uint4*)&T[k * 64 + 8 * sl];
        const __half2* wh = (const __half2*)&w;
        float hv = sx[le][k];
#pragma unroll
        for (int p = 0; p < 4; p++) {
            float2 v = __half22float2(wh[p]);
            acc[2 * p]     = fmaf(hv, v.x, acc[2 * p]);
            acc[2 * p + 1] = fmaf(hv, v.y, acc[2 * p + 1]);
        }
    }
    float* agg = &g_agg[dst * D + 8 * sl];
#pragma unroll
    for (int j = 0; j < 8; j++) atomicAdd(agg + j, acc[j]);
}

// node update: m = lrelu(agg/deg + h@root + conv_b); GRU; h <- new; agg <- 0
__global__ void k_node_update(const float* __restrict__ root,
                              const float* __restrict__ conv_b,
                              const float* __restrict__ bih,
                              const float* __restrict__ bhh) {
    __shared__ float sh[16][D];
    __shared__ float sm[16][D];
    __shared__ float sroot[D][D];
    int nb = blockIdx.x * 16;
    int tid = threadIdx.x;
    int f = tid & 63, ng = tid >> 6;

#pragma unroll
    for (int i = 0; i < 4; i++) {
        int ln = ng + 4 * i;
        sh[ln][f] = g_h[(nb + ln) * D + f];
    }
#pragma unroll
    for (int i = 0; i < 16; i++) {
        int idx = tid + i * 256;
        sroot[idx >> 6][idx & 63] = root[idx];
    }
    __syncthreads();

    float cb = conv_b[f];
#pragma unroll
    for (int i = 0; i < 4; i++) {
        int ln = ng + 4 * i;
        int n = nb + ln;
        float invd = 1.f / fmaxf(g_deg[n], 1.f);
        float acc = g_agg[n * D + f] * invd + cb;
        g_agg[n * D + f] = 0.f;
#pragma unroll 8
        for (int d = 0; d < D; d++) acc += sh[ln][d] * sroot[d][f];
        sm[ln][f] = lrelu(acc);
    }
    __syncthreads();

    float gir[4], giz[4], gin[4], ghr[4], ghz[4], ghn[4];
    float bir = bih[f], biz = bih[D + f], bin = bih[2 * D + f];
    float bhr = bhh[f], bhz = bhh[D + f], bhn = bhh[2 * D + f];
#pragma unroll
    for (int i = 0; i < 4; i++) {
        gir[i] = bir; giz[i] = biz; gin[i] = bin;
        ghr[i] = bhr; ghz[i] = bhz; ghn[i] = bhn;
    }

#pragma unroll 4
    for (int k = 0; k < D; k++) {
        float4 wi = *(const float4*)&g_Wi4[(k * D + f) * 4];
        float4 wh = *(const float4*)&g_Wh4[(k * D + f) * 4];
#pragma unroll
        for (int i = 0; i < 4; i++) {
            int ln = ng + 4 * i;
            float mk = sm[ln][k];
            float hk = sh[ln][k];
            gir[i] += mk * wi.x; giz[i] += mk * wi.y; gin[i] += mk * wi.z;
            ghr[i] += hk * wh.x; ghz[i] += hk * wh.y; ghn[i] += hk * wh.z;
        }
    }

#pragma unroll
    for (int i = 0; i < 4; i++) {
        int ln = ng + 4 * i;
        float r  = sigm(gir[i] + ghr[i]);
        float z  = sigm(giz[i] + ghz[i]);
        float nn = tanhf(gin[i] + r * ghn[i]);
        float hv = (1.f - z) * nn + z * sh[ln][f];
        g_h[(nb + ln) * D + f] = hv;
        g_h_h[(nb + ln) * D + f] = __float2half(hv);
    }
}

// ---------------- set2set + head ----------------

__global__ void k_s2s_init(const float* __restrict__ lbih,
                           const float* __restrict__ lbhh) {
    int t = threadIdx.x;
    if (t < D) {
        float gi = lbih[t]         + lbhh[t];
        float gg = lbih[2 * D + t] + lbhh[2 * D + t];
        float go = lbih[3 * D + t] + lbhh[3 * D + t];
        float cl = sigm(gi) * tanhf(gg);
        g_q[t] = sigm(go) * tanhf(cl);
    }
    if (t < BG) { g_emax[t] = -3.4e38f; g_asum[t] = 0.f; }
    for (int i = t; i < BG * D; i += blockDim.x) g_rpool[i] = 0.f;
}

__global__ void k_dot(const int* __restrict__ batch) {
    int lane = threadIdx.x & 31;
    int warp = threadIdx.x >> 5;
    int n = blockIdx.x * 8 + warp;
    if (n >= N_NODES) return;
    float v = g_h[n * D + lane] * g_q[lane] + g_h[n * D + 32 + lane] * g_q[32 + lane];
#pragma unroll
    for (int o = 16; o > 0; o >>= 1) v += __shfl_down_sync(0xFFFFFFFFu, v, o);
    if (lane == 0) {
        g_e[n] = v;
        atomicMaxF(&g_emax[batch[n]], v);
    }
}

__global__ void k_exp(const int* __restrict__ batch) {
    int n = blockIdx.x * blockDim.x + threadIdx.x;
    if (n >= N_NODES) return;
    int g = batch[n];
    float a = expf(g_e[n] - g_emax[g]);
    g_a[n] = a;
    atomicAdd(&g_asum[g], a);
}

__global__ void k_pool(const int* __restrict__ batch) {
    int idx = blockIdx.x * blockDim.x + threadIdx.x;
    if (idx >= N_NODES * D) return;
    int n = idx >> 6, f = idx & 63;
    int g = batch[n];
    float w = g_a[n] / g_asum[g];
    atomicAdd(&g_rpool[g * D + f], w * g_h[idx]);
}

__global__ void k_out(const float* __restrict__ Wout,
                      const float* __restrict__ bout,
                      float* __restrict__ out) {
    int t = threadIdx.x;
    if (t >= BG * 2) return;
    int b = t >> 1, c = t & 1;
    float acc = bout[c];
#pragma unroll 8
    for (int j = 0; j < D; j++) {
        acc += g_q[j] * Wout[j * 2 + c];
        acc += g_rpool[b * D + j] * Wout[(D + j) * 2 + c];
    }
    out[b * 2 + c] = acc;
}

// ---------------- launch ----------------

extern "C" void kernel_launch(void* const* d_in, const int* in_sizes, int n_in,
                              void* d_out, int out_size) {
    const float* x      = (const float*)d_in[0];
    const float* ea     = (const float*)d_in[1];
    const int*   ei     = (const int*)d_in[2];
    const int*   batch  = (const int*)d_in[3];
    const float* W0     = (const float*)d_in[4];
    const float* b0     = (const float*)d_in[5];
    const float* We1    = (const float*)d_in[6];
    const float* be1    = (const float*)d_in[7];
    const float* We2    = (const float*)d_in[8];
    const float* be2    = (const float*)d_in[9];
    const float* root   = (const float*)d_in[10];
    const float* conv_b = (const float*)d_in[11];
    const float* Wih    = (const float*)d_in[12];
    const float* Whh    = (const float*)d_in[13];
    const float* bih    = (const float*)d_in[14];
    const float* bhh    = (const float*)d_in[15];
    const float* lbih   = (const float*)d_in[18];
    const float* lbhh   = (const float*)d_in[19];
    const float* Wout   = (const float*)d_in[20];
    const float* bout   = (const float*)d_in[21];
    float* out = (float*)d_out;
    (void)in_sizes; (void)n_in; (void)out_size;

    const int TGEMM_SMEM = (256 * 72 + 2 * 64 * 72 + 64 * 264) * (int)sizeof(__half); // 89088
    cudaFuncSetAttribute(k_t_gemm, cudaFuncAttributeMaxDynamicSharedMemorySize, TGEMM_SMEM);

    dim3 tgrid(17, N_NODES / 256);   // 272 blocks = 1 wave @ 2 blocks/SM

    // launch index 3 (ncu capture slot) = first k_msg
    k_prep<<<2176, 256>>>(We2, be2, Wih, Whh);                      // 0
    k_init<<<(N_NODES * D + N_EDGES * D) / 256, 256>>>(x, W0, b0, ea, We1, be1, ei); // 1
    k_t_gemm<<<tgrid, 512, TGEMM_SMEM>>>();                         // 2
    k_msg<<<N_EDGES / 32, 256>>>(ei);                               // 3  <- profiled
    k_node_update<<<N_NODES / 16, 256>>>(root, conv_b, bih, bhh);   // 4

    for (int it = 1; it < 6; it++) {
        k_t_gemm<<<tgrid, 512, TGEMM_SMEM>>>();
        k_msg<<<N_EDGES / 32, 256>>>(ei);
        k_node_update<<<N_NODES / 16, 256>>>(root, conv_b, bih, bhh);
    }

    k_s2s_init<<<1, 256>>>(lbih, lbhh);
    k_dot<<<N_NODES / 8, 256>>>(batch);
    k_exp<<<(N_NODES + 255) / 256, 256>>>(batch);
    k_pool<<<(N_NODES * D) / 256, 256>>>(batch);
    k_out<<<1, 64>>>(Wout, bout, out);
}

// round 13
// speedup vs baseline: 1.0655x; 1.0655x over previous
#include <cuda_runtime.h>
#include <cuda_fp16.h>
#include <math.h>
#include <stdint.h>

#define N_NODES 4096
#define N_EDGES 16384
#define D       64
#define BG      16
#define SLOPE   0.01f

#define TW      4160            // T row width: 4096 (k*64+f) + 64 bias cols
#define TWPAD   4352            // padded to 17*256 for GEMM tiling
#define MAXU    8192            // max work units (<= 4096 + 16384/4)

// ---------------- device scratch ----------------
__device__ __half g_T[(size_t)N_NODES * TW];     // 34 MB per-node transformed table
__device__ __half g_We2RT[TWPAD * D];            // [c][d] reshaped We2 (+bias cols)
__device__ __half g_he_h[N_EDGES * D];
__device__ __half g_h_h[N_NODES * D];            // fp16 mirror of h
__device__ float g_h[N_NODES * D];
__device__ float g_agg[N_NODES * D];
__device__ float g_deg[N_NODES];
__device__ float g_Wi4[D * D * 4];
__device__ float g_Wh4[D * D * 4];
__device__ float g_q[D];
__device__ float g_e[N_NODES];
__device__ float g_a[N_NODES];
__device__ float g_emax[BG];
__device__ float g_asum[BG];
__device__ float g_rpool[BG * D];
// edge grouping (built once per launch; edge_index is loop-invariant)
__device__ int g_scnt[N_NODES];
__device__ int g_rowptr[N_NODES + 1];
__device__ int g_fill[N_NODES];
__device__ int g_eorder[N_EDGES];
__device__ int2 g_units[MAXU];
__device__ int g_nunits;

__device__ __forceinline__ float lrelu(float x) { return x >= 0.f ? x : SLOPE * x; }
__device__ __forceinline__ float sigm(float x)  { return 1.f / (1.f + expf(-x)); }

__device__ __forceinline__ void atomicMaxF(float* addr, float v) {
    int* ai = (int*)addr;
    int old = *ai;
    while (__int_as_float(old) < v) {
        int assumed = old;
        old = atomicCAS(ai, assumed, __float_as_int(v));
        if (old == assumed) break;
    }
}

__device__ __forceinline__ void mma16816(float c[4],
                                         uint32_t a0, uint32_t a1, uint32_t a2, uint32_t a3,
                                         uint32_t b0, uint32_t b1) {
    asm volatile(
        "mma.sync.aligned.m16n8k16.row.col.f32.f16.f16.f32 "
        "{%0,%1,%2,%3}, {%4,%5,%6,%7}, {%8,%9}, {%0,%1,%2,%3};"
        : "+f"(c[0]), "+f"(c[1]), "+f"(c[2]), "+f"(c[3])
        : "r"(a0), "r"(a1), "r"(a2), "r"(a3), "r"(b0), "r"(b1));
}

__device__ __forceinline__ void ldsm_x4(uint32_t& r0, uint32_t& r1,
                                        uint32_t& r2, uint32_t& r3,
                                        const void* smem_ptr) {
    uint32_t addr;
    asm("{ .reg .u64 t; cvta.to.shared.u64 t, %1; cvt.u32.u64 %0, t; }"
        : "=r"(addr) : "l"(smem_ptr));
    asm volatile("ldmatrix.sync.aligned.m8n8.x4.shared.b16 {%0,%1,%2,%3}, [%4];"
                 : "=r"(r0), "=r"(r1), "=r"(r2), "=r"(r3) : "r"(addr));
}

// ---------------- prep kernels ----------------

// sections: [0,1088) we2rt | [1088,1152) gru | [1152,2176) zero agg/deg/scnt + src hist
__global__ void k_prep(const float* __restrict__ We2, const float* __restrict__ be2,
                       const float* __restrict__ Wih, const float* __restrict__ Whh) {
    int b = blockIdx.x;
    int t = threadIdx.x;
    if (b < 1088) {
        int idx = b * 256 + t;                 // < TWPAD*D
        int d = idx & 63, c = idx >> 6;
        float v = 0.f;
        if (c < 4096) {
            int k = c >> 6, f = c & 63;
            v = We2[k * 4096 + d * 64 + f];
        } else if (c < TW) {
            int f = c - 4096;
            v = be2[d * 64 + f];
        }
        g_We2RT[c * D + d] = __float2half(v);
    } else if (b < 1152) {
        int idx = (b - 1088) * 256 + t;        // < D*D*4
        int gg = idx & 3, f = (idx >> 2) & 63, k = idx >> 8;
        float vi = 0.f, vh = 0.f;
        if (gg < 3) {
            vi = Wih[(gg * 64 + f) * 64 + k];
            vh = Whh[(gg * 64 + f) * 64 + k];
        }
        g_Wi4[idx] = vi;
        g_Wh4[idx] = vh;
    } else {
        int idx = (b - 1152) * 256 + t;        // < N_NODES*D
        g_agg[idx] = 0.f;
        if (idx < N_NODES) { g_deg[idx] = 0.f; g_scnt[idx] = 0; }
        if (idx == 0) g_nunits = 0;
    }
}

// node init + edge init + dst-deg + src-hist
__global__ void k_init(const float* __restrict__ x,
                       const float* __restrict__ W0,
                       const float* __restrict__ b0,
                       const float* __restrict__ ea,
                       const float* __restrict__ We1,
                       const float* __restrict__ be1,
                       const int* __restrict__ ei) {
    int gidx = blockIdx.x * blockDim.x + threadIdx.x;
    if (gidx < N_NODES * D) {
        int n = gidx >> 6, f = gidx & 63;
        float acc = b0[f];
        acc += x[n * 3 + 0] * W0[0 * D + f];
        acc += x[n * 3 + 1] * W0[1 * D + f];
        acc += x[n * 3 + 2] * W0[2 * D + f];
        float v = lrelu(acc);
        g_h[gidx] = v;
        g_h_h[gidx] = __float2half(v);
    } else {
        int idx = gidx - N_NODES * D;
        int e = idx >> 6, f = idx & 63;
        float acc = be1[f];
        acc += ea[e * 4 + 0] * We1[0 * D + f];
        acc += ea[e * 4 + 1] * We1[1 * D + f];
        acc += ea[e * 4 + 2] * We1[2 * D + f];
        acc += ea[e * 4 + 3] * We1[3 * D + f];
        g_he_h[idx] = __float2half(lrelu(acc));
        if (f == 0) {
            atomicAdd(&g_deg[ei[N_EDGES + e]], 1.f);
            atomicAdd(&g_scnt[ei[e]], 1);
        }
    }
}

// exclusive scan of scnt -> rowptr; zero fill; build work units (<=4 edges each)
__global__ void k_scan() {
    __shared__ int ssum[1024];
    int t = threadIdx.x;
    int s0 = g_scnt[4 * t], s1 = g_scnt[4 * t + 1];
    int s2 = g_scnt[4 * t + 2], s3 = g_scnt[4 * t + 3];
    int loc = s0 + s1 + s2 + s3;
    ssum[t] = loc;
    __syncthreads();
    for (int off = 1; off < 1024; off <<= 1) {
        int v = (t >= off) ? ssum[t - off] : 0;
        __syncthreads();
        ssum[t] += v;
        __syncthreads();
    }
    int base = ssum[t] - loc;
    int r[4]; int s[4] = {s0, s1, s2, s3};
    r[0] = base; r[1] = base + s0; r[2] = r[1] + s1; r[3] = r[2] + s2;
#pragma unroll
    for (int i = 0; i < 4; i++) {
        int n = 4 * t + i;
        g_rowptr[n] = r[i];
        g_fill[n] = 0;
        int c = s[i];
        int nu = (c + 3) >> 2;
        if (nu > 0) {
            int ub = atomicAdd(&g_nunits, nu);
            for (int bb = 0; bb < nu; bb++) {
                int cnt = c - 4 * bb; if (cnt > 4) cnt = 4;
                g_units[ub + bb] = make_int2(n | (cnt << 20), r[i] + 4 * bb);
            }
        }
    }
    if (t == 1023) g_rowptr[N_NODES] = ssum[1023];
}

// scatter edge ids into src-grouped order
__global__ void k_fill(const int* __restrict__ ei) {
    int e = blockIdx.x * blockDim.x + threadIdx.x;
    if (e >= N_EDGES) return;
    int src = ei[e];
    int pos = atomicAdd(&g_fill[src], 1);
    g_eorder[g_rowptr[src] + pos] = e;
}

// ---------------- per-iteration T GEMM (R11 version) ----------------
__global__ void __launch_bounds__(512, 2) k_t_gemm() {
    extern __shared__ __half smem[];
    __half* sBT = smem;                 // [256][72]
    __half* sA  = smem + 256 * 72;      // [64][72]
    __half* sSt = smem + 320 * 72;      // [64][264]
    int nbase = blockIdx.x * 256;
    int mbase0 = blockIdx.y * 256;
    int tid = threadIdx.x;

#pragma unroll
    for (int i = 0; i < 4; i++) {
        int u = tid + i * 512;
        int row = u >> 3, ch = u & 7;
        *(uint4*)&sBT[row * 72 + ch * 8] = *(const uint4*)&g_We2RT[(nbase + row) * D + ch * 8];
    }

    int warp = tid >> 5, lane = tid & 31;
    int wm = warp & 1, wn = warp >> 1;
    int g = lane >> 2, tig = lane & 3;
    int a_row = (lane & 7) + ((lane & 8) ? 8 : 0);
    int a_col8 = (lane & 16) ? 8 : 0;
    int b_row = (lane & 7) + ((lane & 16) ? 8 : 0);
    int b_col8 = (lane & 8) ? 8 : 0;

#pragma unroll
    for (int ms = 0; ms < 4; ms++) {
        int mbase = mbase0 + ms * 64;
        __syncthreads();
        {
            int row = tid >> 3, ch = tid & 7;
            *(uint4*)&sA[row * 72 + ch * 8] = *(const uint4*)&g_h_h[(mbase + row) * D + ch * 8];
        }
        __syncthreads();

        float c[2][4][4];
#pragma unroll
        for (int t = 0; t < 2; t++)
#pragma unroll
            for (int j = 0; j < 4; j++)
                c[t][j][0] = c[t][j][1] = c[t][j][2] = c[t][j][3] = 0.f;

#pragma unroll
        for (int s = 0; s < 4; s++) {
            int k0 = s * 16;
            uint32_t a[2][4], b[2][4];
#pragma unroll
            for (int t = 0; t < 2; t++)
                ldsm_x4(a[t][0], a[t][1], a[t][2], a[t][3],
                        &sA[(wm * 32 + t * 16 + a_row) * 72 + k0 + a_col8]);
#pragma unroll
            for (int jp = 0; jp < 2; jp++)
                ldsm_x4(b[jp][0], b[jp][1], b[jp][2], b[jp][3],
                        &sBT[(wn * 32 + jp * 16 + b_row) * 72 + k0 + b_col8]);
#pragma unroll
            for (int t = 0; t < 2; t++)
#pragma unroll
                for (int jp = 0; jp < 2; jp++) {
                    mma16816(c[t][2 * jp],     a[t][0], a[t][1], a[t][2], a[t][3],
                             b[jp][0], b[jp][1]);
                    mma16816(c[t][2 * jp + 1], a[t][0], a[t][1], a[t][2], a[t][3],
                             b[jp][2], b[jp][3]);
                }
        }

#pragma unroll
        for (int t = 0; t < 2; t++)
#pragma unroll
            for (int j = 0; j < 4; j++) {
                int col = wn * 32 + j * 8 + 2 * tig;
                int r0 = wm * 32 + t * 16 + g;
                *(__half2*)&sSt[r0 * 264 + col] = __floats2half2_rn(c[t][j][0], c[t][j][1]);
                *(__half2*)&sSt[(r0 + 8) * 264 + col] = __floats2half2_rn(c[t][j][2], c[t][j][3]);
            }
        __syncthreads();

#pragma unroll
        for (int i = 0; i < 4; i++) {
            int u = tid + i * 512;
            int row = u >> 5, seg = u & 31;
            int col = nbase + seg * 8;
            if (col < TW)
                *(uint4*)&g_T[(size_t)(mbase + row) * TW + col] =
                    *(uint4*)&sSt[row * 264 + seg * 8];
        }
    }
}

// ---------------- grouped msg ----------------
// One warp per unit (<=4 edges sharing src). Per k: 1 LDG.32 (warp covers the
// 128B T row) + 4 smem broadcasts + 8 FMA -> serves 4 edges.
__global__ void __launch_bounds__(256) k_msg(const int* __restrict__ ei) {
    __shared__ float sx[8][4][64];
    int warp = threadIdx.x >> 5, lane = threadIdx.x & 31;
    int uid = blockIdx.x * 8 + warp;
    if (uid >= g_nunits) return;
    int2 u = g_units[uid];
    int src = u.x & 0xFFFFF;
    int cnt = u.x >> 20;
    int start = u.y;

    int dsts[4];
#pragma unroll
    for (int i = 0; i < 4; i++) {
        if (i < cnt) {
            int e = g_eorder[start + i];
            dsts[i] = ei[N_EDGES + e];
            uint32_t v = *(const uint32_t*)&g_he_h[e * D + 2 * lane];
            float2 f = __half22float2(*(__half2*)&v);
            *(float2*)&sx[warp][i][2 * lane] = f;
        } else {
            dsts[i] = -1;
            *(float2*)&sx[warp][i][2 * lane] = make_float2(0.f, 0.f);
        }
    }
    __syncwarp();

    const __half2* __restrict__ T = (const __half2*)(g_T + (size_t)src * TW);
    float2 b = __half22float2(T[2048 + lane]);   // bias cols
    float acc[4][2];
#pragma unroll
    for (int i = 0; i < 4; i++) { acc[i][0] = b.x; acc[i][1] = b.y; }

#pragma unroll 8
    for (int k = 0; k < D; k++) {
        float2 w = __half22float2(T[k * 32 + lane]);
#pragma unroll
        for (int i = 0; i < 4; i++) {
            float hv = sx[warp][i][k];
            acc[i][0] = fmaf(hv, w.x, acc[i][0]);
            acc[i][1] = fmaf(hv, w.y, acc[i][1]);
        }
    }

#pragma unroll
    for (int i = 0; i < 4; i++) {
        if (i < cnt) {
            atomicAdd(&g_agg[dsts[i] * D + 2 * lane],     acc[i][0]);
            atomicAdd(&g_agg[dsts[i] * D + 2 * lane + 1], acc[i][1]);
        }
    }
}

// ---------------- node update (R11 version) ----------------
__global__ void k_node_update(const float* __restrict__ root,
                              const float* __restrict__ conv_b,
                              const float* __restrict__ bih,
                              const float* __restrict__ bhh) {
    __shared__ float sh[16][D];
    __shared__ float sm[16][D];
    __shared__ float sroot[D][D];
    int nb = blockIdx.x * 16;
    int tid = threadIdx.x;
    int f = tid & 63, ng = tid >> 6;

#pragma unroll
    for (int i = 0; i < 4; i++) {
        int ln = ng + 4 * i;
        sh[ln][f] = g_h[(nb + ln) * D + f];
    }
#pragma unroll
    for (int i = 0; i < 16; i++) {
        int idx = tid + i * 256;
        sroot[idx >> 6][idx & 63] = root[idx];
    }
    __syncthreads();

    float cb = conv_b[f];
#pragma unroll
    for (int i = 0; i < 4; i++) {
        int ln = ng + 4 * i;
        int n = nb + ln;
        float invd = 1.f / fmaxf(g_deg[n], 1.f);
        float acc = g_agg[n * D + f] * invd + cb;
        g_agg[n * D + f] = 0.f;
#pragma unroll 8
        for (int d = 0; d < D; d++) acc += sh[ln][d] * sroot[d][f];
        sm[ln][f] = lrelu(acc);
    }
    __syncthreads();

    float gir[4], giz[4], gin[4], ghr[4], ghz[4], ghn[4];
    float bir = bih[f], biz = bih[D + f], bin = bih[2 * D + f];
    float bhr = bhh[f], bhz = bhh[D + f], bhn = bhh[2 * D + f];
#pragma unroll
    for (int i = 0; i < 4; i++) {
        gir[i] = bir; giz[i] = biz; gin[i] = bin;
        ghr[i] = bhr; ghz[i] = bhz; ghn[i] = bhn;
    }

#pragma unroll 4
    for (int k = 0; k < D; k++) {
        float4 wi = *(const float4*)&g_Wi4[(k * D + f) * 4];
        float4 wh = *(const float4*)&g_Wh4[(k * D + f) * 4];
#pragma unroll
        for (int i = 0; i < 4; i++) {
            int ln = ng + 4 * i;
            float mk = sm[ln][k];
            float hk = sh[ln][k];
            gir[i] += mk * wi.x; giz[i] += mk * wi.y; gin[i] += mk * wi.z;
            ghr[i] += hk * wh.x; ghz[i] += hk * wh.y; ghn[i] += hk * wh.z;
        }
    }

#pragma unroll
    for (int i = 0; i < 4; i++) {
        int ln = ng + 4 * i;
        float r  = sigm(gir[i] + ghr[i]);
        float z  = sigm(giz[i] + ghz[i]);
        float nn = tanhf(gin[i] + r * ghn[i]);
        float hv = (1.f - z) * nn + z * sh[ln][f];
        g_h[(nb + ln) * D + f] = hv;
        g_h_h[(nb + ln) * D + f] = __float2half(hv);
    }
}

// ---------------- set2set + head ----------------

__global__ void k_s2s_init(const float* __restrict__ lbih,
                           const float* __restrict__ lbhh) {
    int t = threadIdx.x;
    if (t < D) {
        float gi = lbih[t]         + lbhh[t];
        float gg = lbih[2 * D + t] + lbhh[2 * D + t];
        float go = lbih[3 * D + t] + lbhh[3 * D + t];
        float cl = sigm(gi) * tanhf(gg);
        g_q[t] = sigm(go) * tanhf(cl);
    }
    if (t < BG) { g_emax[t] = -3.4e38f; g_asum[t] = 0.f; }
    for (int i = t; i < BG * D; i += blockDim.x) g_rpool[i] = 0.f;
}

__global__ void k_dot(const int* __restrict__ batch) {
    int lane = threadIdx.x & 31;
    int warp = threadIdx.x >> 5;
    int n = blockIdx.x * 8 + warp;
    if (n >= N_NODES) return;
    float v = g_h[n * D + lane] * g_q[lane] + g_h[n * D + 32 + lane] * g_q[32 + lane];
#pragma unroll
    for (int o = 16; o > 0; o >>= 1) v += __shfl_down_sync(0xFFFFFFFFu, v, o);
    if (lane == 0) {
        g_e[n] = v;
        atomicMaxF(&g_emax[batch[n]], v);
    }
}

__global__ void k_exp(const int* __restrict__ batch) {
    int n = blockIdx.x * blockDim.x + threadIdx.x;
    if (n >= N_NODES) return;
    int g = batch[n];
    float a = expf(g_e[n] - g_emax[g]);
    g_a[n] = a;
    atomicAdd(&g_asum[g], a);
}

__global__ void k_pool(const int* __restrict__ batch) {
    int idx = blockIdx.x * blockDim.x + threadIdx.x;
    if (idx >= N_NODES * D) return;
    int n = idx >> 6, f = idx & 63;
    int g = batch[n];
    float w = g_a[n] / g_asum[g];
    atomicAdd(&g_rpool[g * D + f], w * g_h[idx]);
}

__global__ void k_out(const float* __restrict__ Wout,
                      const float* __restrict__ bout,
                      float* __restrict__ out) {
    int t = threadIdx.x;
    if (t >= BG * 2) return;
    int b = t >> 1, c = t & 1;
    float acc = bout[c];
#pragma unroll 8
    for (int j = 0; j < D; j++) {
        acc += g_q[j] * Wout[j * 2 + c];
        acc += g_rpool[b * D + j] * Wout[(D + j) * 2 + c];
    }
    out[b * 2 + c] = acc;
}

// ---------------- launch ----------------

extern "C" void kernel_launch(void* const* d_in, const int* in_sizes, int n_in,
                              void* d_out, int out_size) {
    const float* x      = (const float*)d_in[0];
    const float* ea     = (const float*)d_in[1];
    const int*   ei     = (const int*)d_in[2];
    const int*   batch  = (const int*)d_in[3];
    const float* W0     = (const float*)d_in[4];
    const float* b0     = (const float*)d_in[5];
    const float* We1    = (const float*)d_in[6];
    const float* be1    = (const float*)d_in[7];
    const float* We2    = (const float*)d_in[8];
    const float* be2    = (const float*)d_in[9];
    const float* root   = (const float*)d_in[10];
    const float* conv_b = (const float*)d_in[11];
    const float* Wih    = (const float*)d_in[12];
    const float* Whh    = (const float*)d_in[13];
    const float* bih    = (const float*)d_in[14];
    const float* bhh    = (const float*)d_in[15];
    const float* lbih   = (const float*)d_in[18];
    const float* lbhh   = (const float*)d_in[19];
    const float* Wout   = (const float*)d_in[20];
    const float* bout   = (const float*)d_in[21];
    float* out = (float*)d_out;
    (void)in_sizes; (void)n_in; (void)out_size;

    const int TGEMM_SMEM = (256 * 72 + 64 * 72 + 64 * 264) * (int)sizeof(__half); // 79872
    cudaFuncSetAttribute(k_t_gemm, cudaFuncAttributeMaxDynamicSharedMemorySize, TGEMM_SMEM);

    dim3 tgrid(17, N_NODES / 256);   // 272 blocks = 1 wave @ 2 blocks/SM

    k_prep<<<2176, 256>>>(We2, be2, Wih, Whh);                      // 0
    k_init<<<(N_NODES * D + N_EDGES * D) / 256, 256>>>(x, W0, b0, ea, We1, be1, ei); // 1
    k_scan<<<1, 1024>>>();                                          // 2
    k_t_gemm<<<tgrid, 512, TGEMM_SMEM>>>();                         // 3  <- profiled
    k_fill<<<N_EDGES / 256, 256>>>(ei);                             // 4
    k_msg<<<MAXU / 8, 256>>>(ei);                                   // 5
    k_node_update<<<N_NODES / 16, 256>>>(root, conv_b, bih, bhh);   // 6

    for (int it = 1; it < 6; it++) {
        k_t_gemm<<<tgrid, 512, TGEMM_SMEM>>>();
        k_msg<<<MAXU / 8, 256>>>(ei);
        k_node_update<<<N_NODES / 16, 256>>>(root, conv_b, bih, bhh);
    }

    k_s2s_init<<<1, 256>>>(lbih, lbhh);
    k_dot<<<N_NODES / 8, 256>>>(batch);
    k_exp<<<(N_NODES + 255) / 256, 256>>>(batch);
    k_pool<<<(N_NODES * D) / 256, 256>>>(batch);
    k_out<<<1, 64>>>(Wout, bout, out);
}